// round 15
// baseline (speedup 1.0000x reference)
#include <cuda_runtime.h>
#include <cuda_fp16.h>
#include <mma.h>
#include <math.h>

using namespace nvcuda;

#define N_NODES 100000
#define IN_C 128
#define HID_C 128
#define OUT_C 64
#define N_EDGES 1600000

#define SCAN_BLK 512
#define NB1 ((N_NODES + SCAN_BLK - 1) / SCAN_BLK)   // 196

// ---------------- scratch (device globals: no allocations allowed) ----------
__device__ __align__(16) float  g_dinv[N_NODES];
__device__ __align__(16) __half g_h1[(size_t)N_NODES * HID_C];  // x @ W1 (fp16)
__device__ __align__(16) __half g_a1[(size_t)N_NODES * HID_C];  // layer-1 out (fp16)
__device__ __align__(16) __half g_h2[(size_t)N_NODES * OUT_C];  // relu(a1) @ W2 (fp16)
__device__ __align__(16) int2   g_csre[N_EDGES];     // packed {row, bits(dinv[row])}
__device__ __align__(16) int    g_cnt[N_NODES];      // per-col degree (no self-loop)
__device__ __align__(16) int    g_incl[N_NODES];     // inclusive scan within block
__device__ __align__(16) int    g_part[256];         // block partial sums
__device__ __align__(16) int    g_partoff[256];      // exclusive block offsets
__device__ __align__(16) int    g_ptr[N_NODES + 1];  // CSR pointers (by col)
__device__ __align__(16) int    g_cur[N_NODES];      // fill cursors
__device__ int g_is64;

// ---------------- edge decode (shared by hist + fill) --------------------------
__device__ __forceinline__ void decode_edge(const void* __restrict__ ei, int e,
                                            int& r, int& c) {
    if (g_is64) {
        const long long* p = (const long long*)ei;
        r = (int)p[e];
        c = (int)p[N_EDGES + e];
    } else {
        const int* p = (const int*)ei;
        r = p[e];
        c = p[N_EDGES + e];
    }
    r = min(max(r, 0), N_NODES - 1);
    c = min(max(c, 0), N_NODES - 1);
}

// int64 layout: odd 32-bit words all zero (indices < 2^17). 32 threads, ballot.
__global__ void detect_kernel(const unsigned int* __restrict__ ei32) {
    int t = threadIdx.x;
    unsigned nz = (ei32[2 * t + 1] != 0u) ? 1u : 0u;
    unsigned m = __ballot_sync(0xffffffffu, nz);
    if (t == 0) g_is64 = (m == 0u) ? 1 : 0;
}

__global__ void zero_cnt_kernel() {
    int i = blockIdx.x * blockDim.x + threadIdx.x;
    if (i < N_NODES) g_cnt[i] = 0;
}

__global__ void hist_kernel(const void* __restrict__ ei) {
    int e = blockIdx.x * blockDim.x + threadIdx.x;
    if (e >= N_EDGES) return;
    int r, c;
    decode_edge(ei, e, r, c);
    atomicAdd(&g_cnt[c], 1);
}

// ---------------- prefix scan + CSR fill --------------------------------------
__global__ __launch_bounds__(SCAN_BLK) void scan1_kernel() {
    __shared__ int s[SCAN_BLK];
    int t = threadIdx.x;
    int i = blockIdx.x * SCAN_BLK + t;
    int v = (i < N_NODES) ? g_cnt[i] : 0;
    s[t] = v;
    __syncthreads();
    for (int off = 1; off < SCAN_BLK; off <<= 1) {
        int add = (t >= off) ? s[t - off] : 0;
        __syncthreads();
        s[t] += add;
        __syncthreads();
    }
    if (i < N_NODES) g_incl[i] = s[t];
    if (t == SCAN_BLK - 1) g_part[blockIdx.x] = s[t];
}

__global__ __launch_bounds__(256) void scan2_kernel() {
    __shared__ int s[256];
    int t = threadIdx.x;
    int v = (t < NB1) ? g_part[t] : 0;
    s[t] = v;
    __syncthreads();
    for (int off = 1; off < 256; off <<= 1) {
        int add = (t >= off) ? s[t - off] : 0;
        __syncthreads();
        s[t] += add;
        __syncthreads();
    }
    g_partoff[t] = s[t] - v;   // exclusive
}

__global__ void scan3_kernel() {
    int i = blockIdx.x * blockDim.x + threadIdx.x;
    if (i >= N_NODES) return;
    int cnt  = g_cnt[i];
    int excl = g_partoff[i / SCAN_BLK] + g_incl[i] - cnt;
    g_ptr[i] = excl;
    g_cur[i] = excl;
    g_dinv[i] = rsqrtf((float)cnt + 1.0f);
    if (i == 0) g_ptr[N_NODES] = N_EDGES;
}

__global__ void csr_fill_kernel(const void* __restrict__ ei) {
    int e = blockIdx.x * blockDim.x + threadIdx.x;
    if (e >= N_EDGES) return;
    int r, c;
    decode_edge(ei, e, r, c);
    int pos = atomicAdd(&g_cur[c], 1);
    g_csre[pos] = make_int2(r, __float_as_int(g_dinv[r]));
}

// ---------------- GEMM via tensor cores (wmma, fp16 in / fp32 acc) ------------
// LAYER==1: H1 = fp16(x) @ fp16(W1);  LAYER==2: H2 = relu(a1) @ fp16(W2)
// Block: 128 threads (4 warps), 64-row M-tile, K chunked at 64.
template <int LAYER>
__global__ __launch_bounds__(128) void gemm_hmma_kernel(
    const float* __restrict__ X,       // used only for LAYER==1
    const float* __restrict__ W)
{
    constexpr int FIN  = 128;
    constexpr int FOUT = (LAYER == 1) ? HID_C : OUT_C;
    constexpr int MT   = 64;
    constexpr int KC   = 64;
    constexpr int NF   = FOUT / 16;                    // 8 / 4 N-fragments per warp
    constexpr int S_AB = MT * KC * 2 + KC * FOUT * 2;  // A + W halves
    constexpr int S_O  = MT * FOUT * 4;                // f32 output staging
    constexpr int SBYTES = (S_AB > S_O) ? S_AB : S_O;  // 32KB / 16KB

    __shared__ __align__(16) char raw[SBYTES];
    __half* sA = (__half*)raw;                 // [MT][KC]
    __half* sW = (__half*)(raw + MT * KC * 2); // [KC][FOUT]
    float*  sO = (float*)raw;                  // [MT][FOUT]

    const int tid  = threadIdx.x;
    const int warp = tid >> 5;
    const int n0   = blockIdx.x * MT;

    wmma::fragment<wmma::accumulator, 16, 16, 16, float> acc[NF];
    #pragma unroll
    for (int nf = 0; nf < NF; nf++) wmma::fill_fragment(acc[nf], 0.0f);

    for (int k0 = 0; k0 < FIN; k0 += KC) {
        __syncthreads();   // protect prior-iteration smem reads
        // stage A tile [MT][KC] as fp16 (zero-pad rows past N_NODES)
        #pragma unroll
        for (int i = tid; i < MT * KC / 4; i += 128) {
            int row = i / (KC / 4);
            int q   = i % (KC / 4);
            int n   = n0 + row;
            __half2 h0, h1;
            if (LAYER == 1) {
                float4 f = make_float4(0.f, 0.f, 0.f, 0.f);
                if (n < N_NODES)
                    f = *(const float4*)(X + (size_t)n * FIN + k0 + q * 4);
                h0 = __floats2half2_rn(f.x, f.y);
                h1 = __floats2half2_rn(f.z, f.w);
            } else {
                uint2 u = make_uint2(0u, 0u);
                if (n < N_NODES)
                    u = *(const uint2*)(g_a1 + (size_t)n * FIN + k0 + q * 4);
                __half2 z = __float2half2_rn(0.0f);
                h0 = __hmax2(*(__half2*)&u.x, z);   // relu
                h1 = __hmax2(*(__half2*)&u.y, z);
            }
            __half2* d = (__half2*)(sA + row * KC + q * 4);
            d[0] = h0;
            d[1] = h1;
        }
        // stage W chunk [KC][FOUT] fp32 -> fp16
        #pragma unroll
        for (int i = tid; i < KC * FOUT / 2; i += 128) {
            float2 f = ((const float2*)(W + (size_t)k0 * FOUT))[i];
            ((__half2*)sW)[i] = __floats2half2_rn(f.x, f.y);
        }
        __syncthreads();

        #pragma unroll
        for (int k1 = 0; k1 < KC; k1 += 16) {
            wmma::fragment<wmma::matrix_a, 16, 16, 16, __half, wmma::row_major> a;
            wmma::load_matrix_sync(a, sA + (warp * 16) * KC + k1, KC);
            #pragma unroll
            for (int nf = 0; nf < NF; nf++) {
                wmma::fragment<wmma::matrix_b, 16, 16, 16, __half, wmma::row_major> b;
                wmma::load_matrix_sync(b, sW + k1 * FOUT + nf * 16, FOUT);
                wmma::mma_sync(acc[nf], a, b, acc[nf]);
            }
        }
    }

    __syncthreads();
    #pragma unroll
    for (int nf = 0; nf < NF; nf++)
        wmma::store_matrix_sync(sO + (warp * 16) * FOUT + nf * 16, acc[nf],
                                FOUT, wmma::mem_row_major);
    __syncthreads();

    __half* Hout = (LAYER == 1) ? g_h1 : g_h2;
    #pragma unroll
    for (int i = tid; i < MT * FOUT / 2; i += 128) {
        int row = i / (FOUT / 2);
        int p   = i % (FOUT / 2);
        int n   = n0 + row;
        if (n < N_NODES) {
            float2 f = ((const float2*)sO)[i];
            ((__half2*)(Hout + (size_t)n * FOUT))[p] = __floats2half2_rn(f.x, f.y);
        }
    }
}

// ---------------- CSR gather: one WARP per destination node -------------------
// agg[c] = dinv[c] * sum_j dinv[r_j] * H[r_j]  +  dinv[c]^2 * H[c]  +  bias
template <int FOUT, bool OUT_HALF>
__global__ __launch_bounds__(256) void gather_kernel(
    const __half* __restrict__ H,
    const float* __restrict__ bias,
    void* __restrict__ Aout)
{
    constexpr int VEC = FOUT / 32;   // halves per lane: 4 or 2
    const int node = (blockIdx.x * 256 + threadIdx.x) >> 5;
    const int lane = threadIdx.x & 31;
    if (node >= N_NODES) return;

    const int beg = g_ptr[node];
    const int end = g_ptr[node + 1];
    const float dc = g_dinv[node];

    float acc[VEC];
    #pragma unroll
    for (int v = 0; v < VEC; v++) acc[v] = 0.0f;

    for (int base = beg; base < end; base += 32) {
        int j = base + lane;
        int2 meta = (j < end) ? g_csre[j] : make_int2(0, 0);
        int cnt = min(32, end - base);
        #pragma unroll 8
        for (int i = 0; i < cnt; i++) {
            int   r = __shfl_sync(0xffffffffu, meta.x, i);
            float w = __int_as_float(__shfl_sync(0xffffffffu, meta.y, i));
            const __half* row = H + (size_t)r * FOUT + lane * VEC;
            if (VEC == 4) {
                uint2 u = *(const uint2*)row;
                float2 f0 = __half22float2(*(const __half2*)&u.x);
                float2 f1 = __half22float2(*(const __half2*)&u.y);
                acc[0] = fmaf(w, f0.x, acc[0]);
                acc[1] = fmaf(w, f0.y, acc[1]);
                acc[2] = fmaf(w, f1.x, acc[2]);
                acc[3] = fmaf(w, f1.y, acc[3]);
            } else {
                unsigned u = *(const unsigned*)row;
                float2 f0 = __half22float2(*(const __half2*)&u);
                acc[0] = fmaf(w, f0.x, acc[0]);
                acc[1] = fmaf(w, f0.y, acc[1]);
            }
        }
    }

    const float d2 = dc * dc;
    const __half* srow = H + (size_t)node * FOUT + lane * VEC;
    float o[VEC];
    if (VEC == 4) {
        uint2 u = *(const uint2*)srow;
        float2 s0 = __half22float2(*(const __half2*)&u.x);
        float2 s1 = __half22float2(*(const __half2*)&u.y);
        const float4 b = *(const float4*)(bias + lane * 4);
        o[0] = fmaf(dc, acc[0], fmaf(d2, s0.x, b.x));
        o[1] = fmaf(dc, acc[1], fmaf(d2, s0.y, b.y));
        o[2] = fmaf(dc, acc[2], fmaf(d2, s1.x, b.z));
        o[3] = fmaf(dc, acc[3], fmaf(d2, s1.y, b.w));
    } else {
        unsigned u = *(const unsigned*)srow;
        float2 s0 = __half22float2(*(const __half2*)&u);
        const float2 b = *(const float2*)(bias + lane * 2);
        o[0] = fmaf(dc, acc[0], fmaf(d2, s0.x, b.x));
        o[1] = fmaf(dc, acc[1], fmaf(d2, s0.y, b.y));
    }

    if (OUT_HALF) {
        __half* orow = (__half*)Aout + (size_t)node * FOUT + lane * VEC;
        if (VEC == 4) {
            uint2 u;
            *(__half2*)&u.x = __floats2half2_rn(o[0], o[1]);
            *(__half2*)&u.y = __floats2half2_rn(o[2], o[3]);
            *(uint2*)orow = u;
        } else {
            *(__half2*)orow = __floats2half2_rn(o[0], o[1]);
        }
    } else {
        float* orow = (float*)Aout + (size_t)node * FOUT + lane * VEC;
        if (VEC == 4) {
            *(float4*)orow = make_float4(o[0], o[1], o[2], o[3]);
        } else {
            *(float2*)orow = make_float2(o[0], o[1]);
        }
    }
}

// ---------------- launch ------------------------------------------------------
extern "C" void kernel_launch(void* const* d_in, const int* in_sizes, int n_in,
                              void* d_out, int out_size)
{
    // identify inputs by element count (ordering-proof; all counts distinct)
    const float* x  = nullptr; const void* ei = nullptr;
    const float* W1 = nullptr; const float* b1 = nullptr;
    const float* W2 = nullptr; const float* b2 = nullptr;
    for (int i = 0; i < n_in; i++) {
        switch (in_sizes[i]) {
            case N_NODES * IN_C:   x  = (const float*)d_in[i]; break;
            case 2 * N_EDGES:      ei = d_in[i];               break;
            case IN_C * HID_C:     W1 = (const float*)d_in[i]; break;
            case HID_C:            b1 = (const float*)d_in[i]; break;
            case HID_C * OUT_C:    W2 = (const float*)d_in[i]; break;
            case OUT_C:            b2 = (const float*)d_in[i]; break;
            default: break;
        }
    }
    float* out = (float*)d_out;

    __half* p_h1; cudaGetSymbolAddress((void**)&p_h1, g_h1);
    __half* p_a1; cudaGetSymbolAddress((void**)&p_a1, g_a1);
    __half* p_h2; cudaGetSymbolAddress((void**)&p_h2, g_h2);

    // side stream + fork/join events, created once (first call is uncaptured)
    static cudaStream_t s2 = nullptr;
    static cudaEvent_t ev_fork = nullptr, ev_join = nullptr;
    if (s2 == nullptr) {
        cudaStreamCreateWithFlags(&s2, cudaStreamNonBlocking);
        cudaEventCreateWithFlags(&ev_fork, cudaEventDisableTiming);
        cudaEventCreateWithFlags(&ev_join, cudaEventDisableTiming);
    }

    // ---- fork: CSR build on s2, GEMM1 on default stream (independent) ----
    cudaEventRecord(ev_fork, 0);
    cudaStreamWaitEvent(s2, ev_fork, 0);

    detect_kernel<<<1, 32, 0, s2>>>((const unsigned int*)ei);
    zero_cnt_kernel<<<(N_NODES + 255) / 256, 256, 0, s2>>>();
    hist_kernel<<<(N_EDGES + 255) / 256, 256, 0, s2>>>(ei);
    scan1_kernel<<<NB1, SCAN_BLK, 0, s2>>>();
    scan2_kernel<<<1, 256, 0, s2>>>();
    scan3_kernel<<<(N_NODES + 255) / 256, 256, 0, s2>>>();
    csr_fill_kernel<<<(N_EDGES + 255) / 256, 256, 0, s2>>>(ei);
    cudaEventRecord(ev_join, s2);

    gemm_hmma_kernel<1><<<(N_NODES + 63) / 64, 128>>>(x, W1);   // default stream

    // ---- join: gather1 needs both h1 (default) and CSR+dinv (s2) ----
    cudaStreamWaitEvent(0, ev_join, 0);

    gather_kernel<HID_C, true><<<(N_NODES * 32 + 255) / 256, 256>>>(p_h1, b1, p_a1);

    // layer 2: h2 = relu(a1)@W2 (HMMA) ; out = gather(h2) + self + b2 (fp32)
    gemm_hmma_kernel<2><<<(N_NODES + 63) / 64, 128>>>(nullptr, W2);
    gather_kernel<OUT_C, false><<<(N_NODES * 32 + 255) / 256, 256>>>(p_h2, b2, out);
}